// round 3
// baseline (speedup 1.0000x reference)
#include <cuda_runtime.h>
#include <math.h>

#define D 32
#define NCOL 529          // 1 + 32 + 496
#define LOG2E 1.4426950408889634f

// ---- scratch (no allocations allowed) ----
__device__ float  g_acc[560];    // [0..527] upper-tri X^T X (incl diag), [528..559] column sums
__device__ float  g_stats[64];   // mean[32], inv_sd[32]
__device__ float4 g_pc[512];     // entry t = pair t (linear): {A*log2e, B*log2e, 0.5*log2(1-r^2), packed(i | j<<8)}

__device__ __forceinline__ int tri_idx(int i, int j) {   // i <= j, upper triangle incl diag
    return i * 32 - (i * (i - 1)) / 2 + (j - i);
}

// ---------------- kernel 0: zero accumulators (graph replays must be deterministic) ----------
__global__ void zero_kernel() {
    int t = blockIdx.x * blockDim.x + threadIdx.x;
    if (t < 560) g_acc[t] = 0.0f;
}

// ---------------- kernel 1: circulant-shuffle SYRK: sums + upper-tri X^T X -------------------
__global__ void __launch_bounds__(256) train_kernel(const float* __restrict__ X, int n_train) {
    __shared__ float sacc[560];
    const int tid  = threadIdx.x;
    const int lane = tid & 31;
    const int wg   = blockIdx.x * 8 + (tid >> 5);      // global warp id
    const int W    = gridDim.x * 8;

    for (int t = tid; t < 560; t += 256) sacc[t] = 0.0f;

    float acc[17];
#pragma unroll
    for (int k = 0; k < 17; k++) acc[k] = 0.0f;
    float asum = 0.0f;

    for (int row = wg; row < n_train; row += W) {
        float v = X[row * 32 + lane];
        asum += v;
#pragma unroll
        for (int k = 0; k < 17; k++) {
            float u = __shfl_sync(0xffffffffu, v, (lane + k) & 31);
            acc[k] = fmaf(v, u, acc[k]);
        }
    }
    __syncthreads();   // sacc zeroed before atomics

#pragma unroll
    for (int k = 0; k < 17; k++) {
        int i = lane, j = (lane + k) & 31;
        int lo = min(i, j), hi = max(i, j);
        if (k < 16 || lane < 16)                      // k=16 pairs are duplicated across half-warps
            atomicAdd(&sacc[tri_idx(lo, hi)], acc[k]);
    }
    atomicAdd(&sacc[528 + lane], asum);
    __syncthreads();

    for (int t = tid; t < 560; t += 256)
        atomicAdd(&g_acc[t], sacc[t]);
}

// ---------------- kernel 2: stats + pair-constant table (1 block, 512 threads) ---------------
__global__ void __launch_bounds__(512) prep_kernel(int n_train) {
    __shared__ float mean_s[32], isd_s[32];
    const int t   = threadIdx.x;
    const float fn = (float)n_train;

    if (t < 32) {
        float m   = g_acc[528 + t] / fn;
        float var = (g_acc[tri_idx(t, t)] - fn * m * m) / (fn - 1.0f);
        float isd = 1.0f / sqrtf(var);
        mean_s[t] = m;  isd_s[t] = isd;
        g_stats[t] = m; g_stats[32 + t] = isd;
    }
    __syncthreads();

    // Linear ordering: entry t <-> pair p = t (combinations order), column 33 + t.
    float4 pc;
    if (t < 496) {
        int i = 0, rem = t;
        while (rem >= 31 - i) { rem -= 31 - i; i++; }
        int j = i + 1 + rem;

        float cij = (g_acc[tri_idx(i, j)] - fn * mean_s[i] * mean_s[j]) / (fn - 1.0f);
        float r   = cij * isd_s[i] * isd_s[j];
        float om  = 1.0f - r * r;
        float inv = 1.0f / om;
        pc.x = 0.5f * r * r * inv * LOG2E;      // A' (coeff of zi^2+zj^2, base-2)
        pc.y = -r * inv * LOG2E;                // B' (coeff of zi*zj, base-2)
        pc.z = 0.5f * log2f(om);                // D' = log2(sqrt(1-r^2))
        pc.w = __int_as_float(i | (j << 8));
    } else {
        pc.x = pc.y = pc.z = 0.0f;
        pc.w = __int_as_float(-1);
    }
    g_pc[t] = pc;
}

// ---------------- kernel 3: eval — 4 points per warp, shared table amortized -----------------
__global__ void __launch_bounds__(256) eval_kernel(const float* __restrict__ x,
                                                   float* __restrict__ out, int n_eval) {
    __shared__ float4 pc[512];
    __shared__ float  st[64];
    const int tid = threadIdx.x;
    pc[tid]       = g_pc[tid];
    pc[tid + 256] = g_pc[tid + 256];
    if (tid < 64) st[tid] = g_stats[tid];
    __syncthreads();

    const int lane = tid & 31;
    const int p0   = (blockIdx.x * 8 + (tid >> 5)) * 4;   // 4 points per warp
    if (p0 >= n_eval) return;                              // warp-uniform

    const float mean = st[lane], isd = st[32 + lane];

    float  z[4];
    float* o[4];
    bool   pv[4];
#pragma unroll
    for (int pp = 0; pp < 4; pp++) {
        int pt = p0 + pp;
        pv[pp] = (pt < n_eval);
        int ld = pv[pp] ? pt : 0;
        z[pp] = (x[(size_t)ld * 32 + lane] - mean) * isd;
        o[pp] = out + (size_t)pt * NCOL;
        if (pv[pp]) {
            o[pp][lane] = 1.0f;            // null + singleton columns are all-ones
            if (lane == 0) o[pp][32] = 1.0f;
        }
    }

#pragma unroll
    for (int k = 0; k < 16; k++) {
        float4 c = pc[k * 32 + lane];
        int   w  = __float_as_int(c.w);
        int   ii = w & 31;
        int   jj = (w >> 8) & 31;
        bool  cv = (w >= 0);
        int   col = 33 + k * 32 + lane;
#pragma unroll
        for (int pp = 0; pp < 4; pp++) {
            float zi = __shfl_sync(0xffffffffu, z[pp], ii);
            float zj = __shfl_sync(0xffffffffu, z[pp], jj);
            float s  = fmaf(zi, zi, zj * zj);
            float tt = fmaf(c.x, s, fmaf(c.y, zi * zj, c.z));
            float v  = exp2f(tt);
            if (cv && pv[pp]) o[pp][col] = v;
        }
    }
}

// ---------------- launcher ----------------
extern "C" void kernel_launch(void* const* d_in, const int* in_sizes, int n_in,
                              void* d_out, int out_size) {
    const float* X_train = (const float*)d_in[0];
    const float* x       = (const float*)d_in[1];
    float*       out     = (float*)d_out;

    int n_train = in_sizes[0] / D;
    int n_eval  = in_sizes[1] / D;

    zero_kernel<<<3, 256>>>();
    train_kernel<<<148, 256>>>(X_train, n_train);
    prep_kernel<<<1, 512>>>(n_train);

    int warps  = (n_eval + 3) / 4;            // 4 points per warp
    int blocks = (warps + 7) / 8;             // 8 warps per block
    eval_kernel<<<blocks, 256>>>(x, out, n_eval);
}

// round 5
// speedup vs baseline: 1.5386x; 1.5386x over previous
#include <cuda_runtime.h>
#include <math.h>

#define D 32
#define NCOL 529          // 1 + 32 + 496
#define LOG2E 1.4426950408889634f

// ---- scratch (no allocations allowed) ----
__device__ float  g_acc[560];    // [0..527] upper-tri X^T X (incl diag), [528..559] column sums
__device__ float  g_stats[64];   // mean[32], inv_sd[32]
__device__ float4 g_pc[512];     // entry t = pair t (linear): {A', B', D', packed(i | j<<8)}

__device__ __forceinline__ int tri_idx(int i, int j) {   // i <= j, upper triangle incl diag
    return i * 32 - (i * (i - 1)) / 2 + (j - i);
}

// ---------------- kernel 0: zero accumulators (graph replays must be deterministic) ----------
__global__ void zero_kernel() {
    int t = blockIdx.x * blockDim.x + threadIdx.x;
    if (t < 560) g_acc[t] = 0.0f;
}

// ---------------- kernel 1: circulant-shuffle SYRK, 4-row batched loads (MLP=4) --------------
__global__ void __launch_bounds__(256) train_kernel(const float* __restrict__ X, int n_train) {
    __shared__ float sacc[560];
    const int tid  = threadIdx.x;
    const int lane = tid & 31;
    const int wg   = blockIdx.x * 8 + (tid >> 5);      // global warp id
    const int W    = gridDim.x * 8;

    for (int t = tid; t < 560; t += 256) sacc[t] = 0.0f;

    float acc[17];
#pragma unroll
    for (int k = 0; k < 17; k++) acc[k] = 0.0f;
    float asum = 0.0f;

    int row = wg;
    // 4-deep batched loads: all four LDGs issue before any shuffle consumes them.
    for (; row + 3 * W < n_train; row += 4 * W) {
        float v0 = X[(size_t)row * 32 + lane];
        float v1 = X[(size_t)(row + W) * 32 + lane];
        float v2 = X[(size_t)(row + 2 * W) * 32 + lane];
        float v3 = X[(size_t)(row + 3 * W) * 32 + lane];
        asum += (v0 + v1) + (v2 + v3);
#pragma unroll
        for (int k = 0; k < 17; k++) {
            int src = (lane + k) & 31;
            acc[k] = fmaf(v0, __shfl_sync(0xffffffffu, v0, src), acc[k]);
            acc[k] = fmaf(v1, __shfl_sync(0xffffffffu, v1, src), acc[k]);
            acc[k] = fmaf(v2, __shfl_sync(0xffffffffu, v2, src), acc[k]);
            acc[k] = fmaf(v3, __shfl_sync(0xffffffffu, v3, src), acc[k]);
        }
    }
    for (; row < n_train; row += W) {           // warp-uniform tail
        float v = X[(size_t)row * 32 + lane];
        asum += v;
#pragma unroll
        for (int k = 0; k < 17; k++)
            acc[k] = fmaf(v, __shfl_sync(0xffffffffu, v, (lane + k) & 31), acc[k]);
    }
    __syncthreads();   // sacc zeroed before atomics

#pragma unroll
    for (int k = 0; k < 17; k++) {
        int i = lane, j = (lane + k) & 31;
        int lo = min(i, j), hi = max(i, j);
        if (k < 16 || lane < 16)                // k=16 pairs duplicated across half-warps
            atomicAdd(&sacc[tri_idx(lo, hi)], acc[k]);
    }
    atomicAdd(&sacc[528 + lane], asum);
    __syncthreads();

    for (int t = tid; t < 560; t += 256)
        atomicAdd(&g_acc[t], sacc[t]);
}

// ---------------- kernel 2: stats + pair-constant table (1 block, 512 threads) ---------------
__global__ void __launch_bounds__(512) prep_kernel(int n_train) {
    __shared__ float mean_s[32], isd_s[32];
    const int t   = threadIdx.x;
    const float fn = (float)n_train;

    if (t < 32) {
        float m   = g_acc[528 + t] / fn;
        float var = (g_acc[tri_idx(t, t)] - fn * m * m) / (fn - 1.0f);
        float isd = 1.0f / sqrtf(var);
        mean_s[t] = m;  isd_s[t] = isd;
        g_stats[t] = m; g_stats[32 + t] = isd;
    }
    __syncthreads();

    // Linear ordering: entry t <-> pair p = t (combinations order), column 33 + t.
    float4 pc;
    if (t < 496) {
        int i = 0, rem = t;
        while (rem >= 31 - i) { rem -= 31 - i; i++; }
        int j = i + 1 + rem;

        float cij = (g_acc[tri_idx(i, j)] - fn * mean_s[i] * mean_s[j]) / (fn - 1.0f);
        float r   = cij * isd_s[i] * isd_s[j];
        float om  = 1.0f - r * r;
        float inv = 1.0f / om;
        pc.x = 0.5f * r * r * inv * LOG2E;      // A' (coeff of zi^2+zj^2, base-2)
        pc.y = -r * inv * LOG2E;                // B' (coeff of zi*zj, base-2)
        pc.z = 0.5f * log2f(om);                // D' = log2(sqrt(1-r^2))
        pc.w = __int_as_float(i | (j << 8));
    } else {
        pc.x = pc.y = pc.z = 0.0f;
        pc.w = __int_as_float(-1);
    }
    g_pc[t] = pc;
}

// ---------------- kernel 3: eval — 4 points/warp, spill-free, single base pointer ------------
__global__ void __launch_bounds__(256, 1) eval_kernel(const float* __restrict__ x,
                                                      float* __restrict__ out, int n_eval) {
    __shared__ float4 pc[512];
    __shared__ float  st[64];
    const int tid = threadIdx.x;
    pc[tid]       = g_pc[tid];
    pc[tid + 256] = g_pc[tid + 256];
    if (tid < 64) st[tid] = g_stats[tid];
    __syncthreads();

    const int lane = tid & 31;
    const int p0   = (blockIdx.x * 8 + (tid >> 5)) * 4;   // 4 points per warp
    if (p0 >= n_eval) return;                              // warp-uniform; N_EVAL % 4 == 0

    const float mean = st[lane], isd = st[32 + lane];

    const float* xp = x + (size_t)p0 * 32 + lane;
    float z0 = (xp[0]  - mean) * isd;
    float z1 = (xp[32] - mean) * isd;
    float z2 = (xp[64] - mean) * isd;
    float z3 = (xp[96] - mean) * isd;

    float* o = out + (size_t)p0 * NCOL;
    // null + singleton columns are all-ones (33 per point)
    o[lane] = 1.0f; o[NCOL + lane] = 1.0f; o[2 * NCOL + lane] = 1.0f; o[3 * NCOL + lane] = 1.0f;
    if (lane == 0) {
        o[32] = 1.0f; o[NCOL + 32] = 1.0f; o[2 * NCOL + 32] = 1.0f; o[3 * NCOL + 32] = 1.0f;
    }

#pragma unroll
    for (int k = 0; k < 16; k++) {
        float4 c  = pc[k * 32 + lane];
        int   w   = __float_as_int(c.w);
        int   ii  = w & 31;
        int   jj  = (w >> 8) & 31;
        bool  cv  = (w >= 0);
        int   col = 33 + k * 32 + lane;

        float zi0 = __shfl_sync(0xffffffffu, z0, ii), zj0 = __shfl_sync(0xffffffffu, z0, jj);
        float zi1 = __shfl_sync(0xffffffffu, z1, ii), zj1 = __shfl_sync(0xffffffffu, z1, jj);
        float zi2 = __shfl_sync(0xffffffffu, z2, ii), zj2 = __shfl_sync(0xffffffffu, z2, jj);
        float zi3 = __shfl_sync(0xffffffffu, z3, ii), zj3 = __shfl_sync(0xffffffffu, z3, jj);

        float v0 = exp2f(fmaf(c.x, fmaf(zi0, zi0, zj0 * zj0), fmaf(c.y, zi0 * zj0, c.z)));
        float v1 = exp2f(fmaf(c.x, fmaf(zi1, zi1, zj1 * zj1), fmaf(c.y, zi1 * zj1, c.z)));
        float v2 = exp2f(fmaf(c.x, fmaf(zi2, zi2, zj2 * zj2), fmaf(c.y, zi2 * zj2, c.z)));
        float v3 = exp2f(fmaf(c.x, fmaf(zi3, zi3, zj3 * zj3), fmaf(c.y, zi3 * zj3, c.z)));

        if (cv) {
            o[col]            = v0;
            o[col + NCOL]     = v1;
            o[col + 2 * NCOL] = v2;
            o[col + 3 * NCOL] = v3;
        }
    }
}

// ---------------- launcher ----------------
extern "C" void kernel_launch(void* const* d_in, const int* in_sizes, int n_in,
                              void* d_out, int out_size) {
    const float* X_train = (const float*)d_in[0];
    const float* x       = (const float*)d_in[1];
    float*       out     = (float*)d_out;

    int n_train = in_sizes[0] / D;
    int n_eval  = in_sizes[1] / D;

    zero_kernel<<<3, 256>>>();
    train_kernel<<<148, 256>>>(X_train, n_train);
    prep_kernel<<<1, 512>>>(n_train);

    int warps  = (n_eval + 3) / 4;            // 4 points per warp
    int blocks = (warps + 7) / 8;             // 8 warps per block
    eval_kernel<<<blocks, 256>>>(x, out, n_eval);
}